// round 3
// baseline (speedup 1.0000x reference)
#include <cuda_runtime.h>
#include <math.h>

#define T 32
#define N 512
#define E 64
#define F 64
#define HD 64
#define SLOPE 0.2f

// ---------------- device scratch (no allocations allowed) ----------------
__device__ float g_h[T * N * HD];       // 4 MB
__device__ float g_shyp[T * N];
__device__ float g_sind[T * N];
__device__ float g_emax[T * E];
__device__ float g_einv[T * E];
__device__ float g_ind[T * N * HD];     // 4 MB
__device__ int   g_adj_cnt[N];
__device__ int   g_adj_nbr[N * N];      // 1 MB
__device__ int   g_ne_cnt[N];
__device__ int   g_ne_off[N];
__device__ int   g_ne_lst[N * E];
__device__ int   g_en_cnt[E];
__device__ int   g_en_lst[E * N];
__device__ int   g_wl_n[N * E];
__device__ int   g_wl_e[N * E];
__device__ int   g_nnz;
__device__ int   g_Mhyp;                // 32 * nnz
__device__ int   g_Mtot;                // Mhyp + T*N
__device__ float g_zall[T * N * E + T * N];   // hyper z's then industry z's

// ---------------- fused CSR builders ----------------
__global__ void k_csr(const int* __restrict__ adj, const int* __restrict__ Hm) {
    int b = blockIdx.x;
    int lane = threadIdx.x & 31;
    int wl = threadIdx.x >> 5;
    if (b < 64) {                             // adjacency rows
        int i = b * 8 + wl;
        int cnt = 0;
        #pragma unroll
        for (int c = 0; c < N / 32; c++) {
            int j = c * 32 + lane;
            bool m = adj[i * N + j] != 0;
            unsigned bl = __ballot_sync(0xffffffffu, m);
            if (m) g_adj_nbr[i * N + cnt + __popc(bl & ((1u << lane) - 1u))] = j;
            cnt += __popc(bl);
        }
        if (lane == 0) g_adj_cnt[i] = cnt;
    } else if (b < 128) {                     // node -> member edges
        int n = (b - 64) * 8 + wl;
        int cnt = 0;
        #pragma unroll
        for (int c = 0; c < E / 32; c++) {
            int e = c * 32 + lane;
            bool m = Hm[n * E + e] != 0;
            unsigned bl = __ballot_sync(0xffffffffu, m);
            if (m) g_ne_lst[n * E + cnt + __popc(bl & ((1u << lane) - 1u))] = e;
            cnt += __popc(bl);
        }
        if (lane == 0) g_ne_cnt[n] = cnt;
    } else {                                  // edge -> member nodes
        int e = (b - 128) * 8 + wl;
        int cnt = 0;
        #pragma unroll
        for (int c = 0; c < N / 32; c++) {
            int n = c * 32 + lane;
            bool m = Hm[n * E + e] != 0;
            unsigned bl = __ballot_sync(0xffffffffu, m);
            if (m) g_en_lst[e * N + cnt + __popc(bl & ((1u << lane) - 1u))] = n;
            cnt += __popc(bl);
        }
        if (lane == 0) g_en_cnt[e] = cnt;
    }
}

// ---------------- prefix scan of degrees + flat worklist ----------------
__global__ void k_scan() {
    __shared__ int buf[N];
    int n = threadIdx.x;
    int c = g_ne_cnt[n];
    buf[n] = c;
    __syncthreads();
    #pragma unroll
    for (int o = 1; o < N; o <<= 1) {
        int add = (n >= o) ? buf[n - o] : 0;
        __syncthreads();
        buf[n] += add;
        __syncthreads();
    }
    int off = buf[n] - c;
    g_ne_off[n] = off;
    if (n == N - 1) {
        int nnz = buf[N - 1];
        g_nnz = nnz;
        g_Mhyp = T * nnz;
        g_Mtot = T * nnz + T * N;
    }
    for (int j = 0; j < c; j++) {
        g_wl_n[off + j] = n;
        g_wl_e[off + j] = g_ne_lst[n * E + j];
    }
}

// ---------------- h = x@W (smem-tiled GEMM) + fused s_hyp / s_ind ----------------
__global__ void __launch_bounds__(256) k_h(const float* __restrict__ x,
                                           const float* __restrict__ W,
                                           const float* __restrict__ ah,
                                           const float* __restrict__ ai) {
    __shared__ float xs[32][65];
    __shared__ float ws[64][65];
    int tid = threadIdx.x;
    int r0 = blockIdx.x * 32;

    for (int i = tid; i < 32 * 64; i += 256) {
        int r = i >> 6, c = i & 63;
        xs[r][c] = x[(r0 + r) * F + c];
    }
    for (int i = tid; i < 64 * 64; i += 256) {
        int r = i >> 6, c = i & 63;
        ws[r][c] = W[i];
    }
    __syncthreads();

    int ty = tid >> 4, tx = tid & 15;
    float acc[2][4] = {{0.f,0.f,0.f,0.f},{0.f,0.f,0.f,0.f}};
    #pragma unroll 8
    for (int k = 0; k < 64; k++) {
        float xr0 = xs[ty * 2 + 0][k];
        float xr1 = xs[ty * 2 + 1][k];
        float wv[4];
        #pragma unroll
        for (int j = 0; j < 4; j++) wv[j] = ws[k][tx * 4 + j];
        #pragma unroll
        for (int j = 0; j < 4; j++) {
            acc[0][j] = fmaf(xr0, wv[j], acc[0][j]);
            acc[1][j] = fmaf(xr1, wv[j], acc[1][j]);
        }
    }
    __syncthreads();
    #pragma unroll
    for (int i = 0; i < 2; i++) {
        int r = ty * 2 + i;
        #pragma unroll
        for (int j = 0; j < 4; j++) xs[r][tx * 4 + j] = acc[i][j];
        float4 v = make_float4(acc[i][0], acc[i][1], acc[i][2], acc[i][3]);
        *(float4*)&g_h[(r0 + r) * HD + tx * 4] = v;
    }
    __syncthreads();

    int row = tid >> 3, oct = tid & 7;
    float sh = 0.f, si = 0.f;
    #pragma unroll
    for (int k = 0; k < 8; k++) {
        float v = xs[row][oct * 8 + k];
        sh = fmaf(v, __ldg(&ah[oct * 8 + k]), sh);
        si = fmaf(v, __ldg(&ai[oct * 8 + k]), si);
    }
    #pragma unroll
    for (int o = 4; o > 0; o >>= 1) {
        sh += __shfl_xor_sync(0xffffffffu, sh, o);
        si += __shfl_xor_sync(0xffffffffu, si, o);
    }
    if (oct == 0) {
        g_shyp[r0 + row] = sh >= 0.f ? sh : SLOPE * sh;
        g_sind[r0 + row] = si >= 0.f ? si : SLOPE * si;
    }
}

// ---------------- fused: industry attention + hyperedge stats ----------------
__global__ void __launch_bounds__(256) k_mid() {
    int b = blockIdx.x;
    int tid = threadIdx.x;
    int lane = tid & 31;
    if (b < 4096) {
        __shared__ float smw4[4][512];
        __shared__ float smrA[8];
        __shared__ float smrB[8];
        int g = tid >> 6;
        int d = tid & 63;
        int warp = tid >> 5;
        int row = b * 4 + g;
        int t = row >> 9;
        int i = row & (N - 1);
        int deg = g_adj_cnt[i];
        const int* nbr = g_adj_nbr + i * N;
        const float* si = g_sind + t * N;

        float m = -3.0e38f;
        for (int k = d; k < deg; k += 64) m = fmaxf(m, si[nbr[k]]);
        #pragma unroll
        for (int o = 16; o > 0; o >>= 1) m = fmaxf(m, __shfl_xor_sync(0xffffffffu, m, o));
        if (lane == 0) smrA[warp] = m;
        __syncthreads();
        m = fmaxf(smrA[g * 2], smrA[g * 2 + 1]);

        float s = 0.f;
        for (int k = d; k < deg; k += 64) {
            float w = expf(si[nbr[k]] - m);
            smw4[g][k] = w;
            s += w;
        }
        #pragma unroll
        for (int o = 16; o > 0; o >>= 1) s += __shfl_xor_sync(0xffffffffu, s, o);
        if (lane == 0) smrB[warp] = s;
        __syncthreads();
        float inv = 1.f / (smrB[g * 2] + smrB[g * 2 + 1]);

        const float* hb = g_h + t * N * HD;
        float a0 = 0.f, a1 = 0.f, a2 = 0.f, a3 = 0.f;
        int k = 0;
        for (; k + 4 <= deg; k += 4) {
            int j0 = nbr[k], j1 = nbr[k + 1], j2 = nbr[k + 2], j3 = nbr[k + 3];
            a0 = fmaf(smw4[g][k],     hb[j0 * HD + d], a0);
            a1 = fmaf(smw4[g][k + 1], hb[j1 * HD + d], a1);
            a2 = fmaf(smw4[g][k + 2], hb[j2 * HD + d], a2);
            a3 = fmaf(smw4[g][k + 3], hb[j3 * HD + d], a3);
        }
        for (; k < deg; k++) a0 = fmaf(smw4[g][k], hb[nbr[k] * HD + d], a0);
        g_ind[row * HD + d] = ((a0 + a1) + (a2 + a3)) * inv;
    } else {
        int w = (b - 4096) * 8 + (tid >> 5);
        int t = w / E, e = w % E;
        int cnt = g_en_cnt[e];
        const int* lst = g_en_lst + e * N;
        const float* sh = g_shyp + t * N;
        float m = -3.0e38f;
        for (int i = lane; i < cnt; i += 32) m = fmaxf(m, sh[lst[i]]);
        #pragma unroll
        for (int o = 16; o > 0; o >>= 1) m = fmaxf(m, __shfl_xor_sync(0xffffffffu, m, o));
        float s = 0.f;
        for (int i = lane; i < cnt; i += 32) s += expf(sh[lst[i]] - m);
        #pragma unroll
        for (int o = 16; o > 0; o >>= 1) s += __shfl_xor_sync(0xffffffffu, s, o);
        if (lane == 0) { g_emax[w] = m; g_einv[w] = 1.f / s; }
    }
}

// ---------------- shared GEMM body: 64x64 tile, 64 threads, 8x8 register tile ----------------
__device__ __forceinline__ void score_gemm(const float* __restrict__ Ws,
                                           const float* __restrict__ fs,
                                           int ty, int tx, float acc[8][8]) {
    #pragma unroll 16
    for (int k = 0; k < HD; k++) {
        float fv[8];
        #pragma unroll
        for (int i = 0; i < 8; i++) fv[i] = fs[(ty * 8 + i) * 65 + k];
        float4 w0 = *(const float4*)&Ws[k * HD + tx * 8];
        float4 w1 = *(const float4*)&Ws[k * HD + tx * 8 + 4];
        float wv[8] = {w0.x, w0.y, w0.z, w0.w, w1.x, w1.y, w1.z, w1.w};
        #pragma unroll
        for (int i = 0; i < 8; i++)
            #pragma unroll
            for (int j = 0; j < 8; j++)
                acc[i][j] = fmaf(fv[i], wv[j], acc[i][j]);
    }
}

__device__ __forceinline__ float elu1(float v) { return v > 0.f ? v : expm1f(v); }

// ---------------- phase A: scores for hyperedge instances + industry rows ----------------
__global__ void __launch_bounds__(64) k_scoreA(const float* __restrict__ Wc1g,
                                               const float* __restrict__ bc1g,
                                               const float* __restrict__ wc2g,
                                               const float* __restrict__ bc2g) {
    __shared__ float Ws[HD * HD];
    __shared__ float fs[64 * 65];
    __shared__ float zp[64 * 9];
    int tid = threadIdx.x;
    int ty = tid >> 3, tx = tid & 7;

    for (int i = tid; i < HD * HD; i += 64) Ws[i] = Wc1g[i];
    float bc1r[8], wc2r[8];
    #pragma unroll
    for (int j = 0; j < 8; j++) {
        bc1r[j] = __ldg(&bc1g[tx * 8 + j]);
        wc2r[j] = __ldg(&wc2g[tx * 8 + j]);
    }
    float bc2 = __ldg(&bc2g[0]);
    int Mtot = g_Mtot, Mhyp = g_Mhyp, nnz = g_nnz;
    int ntiles = (Mtot + 63) >> 6;

    for (int tile = blockIdx.x; tile < ntiles; tile += gridDim.x) {
        __syncthreads();
        int row = tile * 64 + tid;
        // fill: thread tid builds feats row tid
        if (row < Mhyp) {
            int t = row / nnz;
            int idx = row - t * nnz;
            int n = g_wl_n[idx], e = g_wl_e[idx];
            float a = expf(g_shyp[t * N + n] - g_emax[t * E + e]) * g_einv[t * E + e];
            const float4* hp = (const float4*)&g_h[(t * N + n) * HD];
            #pragma unroll
            for (int q = 0; q < 16; q++) {
                float4 v = hp[q];
                fs[tid * 65 + q * 4 + 0] = elu1(a * v.x);
                fs[tid * 65 + q * 4 + 1] = elu1(a * v.y);
                fs[tid * 65 + q * 4 + 2] = elu1(a * v.z);
                fs[tid * 65 + q * 4 + 3] = elu1(a * v.w);
            }
        } else if (row < Mtot) {
            const float4* ip = (const float4*)&g_ind[(row - Mhyp) * HD];
            #pragma unroll
            for (int q = 0; q < 16; q++) {
                float4 v = ip[q];
                fs[tid * 65 + q * 4 + 0] = v.x;
                fs[tid * 65 + q * 4 + 1] = v.y;
                fs[tid * 65 + q * 4 + 2] = v.z;
                fs[tid * 65 + q * 4 + 3] = v.w;
            }
        } else {
            #pragma unroll
            for (int q = 0; q < 64; q++) fs[tid * 65 + q] = 0.f;
        }
        __syncthreads();

        float acc[8][8];
        #pragma unroll
        for (int i = 0; i < 8; i++)
            #pragma unroll
            for (int j = 0; j < 8; j++) acc[i][j] = 0.f;
        score_gemm(Ws, fs, ty, tx, acc);

        #pragma unroll
        for (int i = 0; i < 8; i++) {
            float p = 0.f;
            #pragma unroll
            for (int j = 0; j < 8; j++)
                p = fmaf(fmaxf(acc[i][j] + bc1r[j], 0.f), wc2r[j], p);
            zp[(ty * 8 + i) * 9 + tx] = p;
        }
        __syncthreads();
        if (row < Mtot) {
            float z = bc2;
            #pragma unroll
            for (int q = 0; q < 8; q++) z += zp[tid * 9 + q];
            g_zall[row] = z;
        }
    }
}

// ---------------- phase B: y8 build (in fill) + score + final combine ----------------
__global__ void __launch_bounds__(64) k_scoreBfin(float* __restrict__ out,
                                                  const float* __restrict__ Wc1g,
                                                  const float* __restrict__ bc1g,
                                                  const float* __restrict__ wc2g,
                                                  const float* __restrict__ bc2g) {
    __shared__ float Ws[HD * HD];
    __shared__ float fs[64 * 65];
    __shared__ float zp[64 * 9];
    int tid = threadIdx.x;
    int ty = tid >> 3, tx = tid & 7;

    for (int i = tid; i < HD * HD; i += 64) Ws[i] = Wc1g[i];
    float bc1r[8], wc2r[8];
    #pragma unroll
    for (int j = 0; j < 8; j++) {
        bc1r[j] = __ldg(&bc1g[tx * 8 + j]);
        wc2r[j] = __ldg(&wc2g[tx * 8 + j]);
    }
    float bc2 = __ldg(&bc2g[0]);
    int Mhyp = g_Mhyp, nnz = g_nnz;

    int row = blockIdx.x * 64 + tid;          // (t,n) in [0, 16384)
    int t = row >> 9, n = row & (N - 1);
    int deg = g_ne_cnt[n];
    int off = g_ne_off[n];

    // fill: compute y8 row for (t,n)
    {
        float hreg[64];
        const float4* hp = (const float4*)&g_h[row * HD];
        #pragma unroll
        for (int q = 0; q < 16; q++) {
            float4 v = hp[q];
            hreg[q * 4 + 0] = v.x; hreg[q * 4 + 1] = v.y;
            hreg[q * 4 + 2] = v.z; hreg[q * 4 + 3] = v.w;
        }
        float shn = g_shyp[row];
        const float* zb = g_zall + t * nnz + off;
        const int* el = g_ne_lst + n * E;
        float M = -3.0e38f;
        for (int j = 0; j < deg; j++) M = fmaxf(M, zb[j]);
        float y8v[64];
        #pragma unroll
        for (int q = 0; q < 64; q++) y8v[q] = 0.f;
        float S = 0.f;
        for (int j = 0; j < deg; j++) {
            float w = expf(zb[j] - M);
            S += w;
            int e = el[j];
            float a = expf(shn - g_emax[t * E + e]) * g_einv[t * E + e];
            #pragma unroll
            for (int q = 0; q < 64; q++)
                y8v[q] = fmaf(w, elu1(a * hreg[q]), y8v[q]);
        }
        float inv = 1.f / S;
        #pragma unroll
        for (int q = 0; q < 64; q++) fs[tid * 65 + q] = y8v[q] * inv;
    }
    __syncthreads();

    float acc[8][8];
    #pragma unroll
    for (int i = 0; i < 8; i++)
        #pragma unroll
        for (int j = 0; j < 8; j++) acc[i][j] = 0.f;
    score_gemm(Ws, fs, ty, tx, acc);

    #pragma unroll
    for (int i = 0; i < 8; i++) {
        float p = 0.f;
        #pragma unroll
        for (int j = 0; j < 8; j++)
            p = fmaf(fmaxf(acc[i][j] + bc1r[j], 0.f), wc2r[j], p);
        zp[(ty * 8 + i) * 9 + tx] = p;
    }
    __syncthreads();

    // combine: thread tid owns row (t,n)
    float z2 = bc2;
    #pragma unroll
    for (int q = 0; q < 8; q++) z2 += zp[tid * 9 + q];
    float z1 = g_zall[Mhyp + row];
    float m2 = fmaxf(z1, z2);
    float w1 = expf(z1 - m2), w2 = expf(z2 - m2);
    float inv = 1.f / (w1 + w2);
    const float4* ip = (const float4*)&g_ind[row * HD];
    float4* op = (float4*)&out[row * HD];
    #pragma unroll
    for (int q = 0; q < 16; q++) {
        float4 iv = ip[q];
        float4 r;
        r.x = (w1 * iv.x + w2 * fs[tid * 65 + q * 4 + 0]) * inv;
        r.y = (w1 * iv.y + w2 * fs[tid * 65 + q * 4 + 1]) * inv;
        r.z = (w1 * iv.z + w2 * fs[tid * 65 + q * 4 + 2]) * inv;
        r.w = (w1 * iv.w + w2 * fs[tid * 65 + q * 4 + 3]) * inv;
        op[q] = r;
    }
}

// ---------------- launch ----------------
extern "C" void kernel_launch(void* const* d_in, const int* in_sizes, int n_in,
                              void* d_out, int out_size) {
    int off = (n_in >= 11) ? 1 : 0;
    const float* x   = (const float*)d_in[0];
    const int*   Hm  = (const int*)d_in[1];
    const int*   adj = (const int*)d_in[2];
    const float* W   = (const float*)d_in[3 + off];
    const float* ah  = (const float*)d_in[4 + off];
    const float* ai  = (const float*)d_in[5 + off];
    const float* Wc1 = (const float*)d_in[6 + off];
    const float* bc1 = (const float*)d_in[7 + off];
    const float* wc2 = (const float*)d_in[8 + off];
    const float* bc2 = (const float*)d_in[9 + off];
    float* outp = (float*)d_out;

    k_csr<<<136, 256>>>(adj, Hm);
    k_scan<<<1, N>>>();
    k_h<<<T * N / 32, 256>>>(x, W, ah, ai);
    k_mid<<<4096 + 256, 256>>>();
    k_scoreA<<<1024, 64>>>(Wc1, bc1, wc2, bc2);
    k_scoreBfin<<<T * N / 64, 64>>>(outp, Wc1, bc1, wc2, bc2);
}